// round 15
// baseline (speedup 1.0000x reference)
#include <cuda_runtime.h>
#include <cuda_bf16.h>
#include <math.h>
#include <stdint.h>

// ---------------- problem constants ----------------
#define NB 512          // batch
#define ND 512          // embed dim
#define MAX_C 100000
#define CTILE 128       // classes per CTA (M)
#define STILE 256       // samples per CTA tile (N)
#define KCH 64          // K chunk for E tile (double buffered)
#define NCHK (ND / KCH) // 8
#define NCBLK_MAX ((MAX_C + CTILE - 1) / CTILE)   // 782
#define NPART_MAX (NCBLK_MAX * 2)                 // 2 partials per CTA (per warp_m)

// ArcFace constants (margin=0.5, scale=64, t=0.2)
#define ARC_COS_M 0.8775825618903728f
#define ARC_SIN_M 0.479425538604203f
#define ARC_TH   (-0.8775825618903728f)
#define ARC_MM    0.2397127693021015f
#define ARC_EPS   1e-7f
#define ARC_SCALE 64.0f
#define FIX_MAX   90.0f   // > 64*(1.2*1+0.2) = 89.6, absolute logit bound

// ---------------- static scratch ----------------
__device__ float          g_en [NB * ND];     // normalized embeddings fp32
__device__ __nv_bfloat16  g_ebf[NB * ND];     // normalized embeddings bf16
__device__ float          g_phi[NB];
__device__ int            g_gt [NB];
__device__ float          g_part[(size_t)NB * NPART_MAX];  // sum of exp(v-90)
__device__ float          g_samp[NB];
__device__ int            g_gt_is_i32;

// ---------------- PTX helpers (plain-sm_103-safe) ----------------
__device__ __forceinline__ uint32_t s2u(const void* p) {
    uint32_t a;
    asm("{ .reg .u64 t; cvta.to.shared.u64 t, %1; cvt.u32.u64 %0, t; }" : "=r"(a) : "l"(p));
    return a;
}
#define LDSM_X4(r0, r1, r2, r3, addr)                                          \
    asm volatile("ldmatrix.sync.aligned.m8n8.x4.shared.b16 {%0,%1,%2,%3}, [%4];" \
                 : "=r"(r0), "=r"(r1), "=r"(r2), "=r"(r3) : "r"(addr))
__device__ __forceinline__ void mma16816(float* c, const uint32_t* a, const uint32_t* b) {
    asm volatile(
        "mma.sync.aligned.m16n8k16.row.col.f32.bf16.bf16.f32 "
        "{%0,%1,%2,%3}, {%4,%5,%6,%7}, {%8,%9}, {%0,%1,%2,%3};"
        : "+f"(c[0]), "+f"(c[1]), "+f"(c[2]), "+f"(c[3])
        : "r"(a[0]), "r"(a[1]), "r"(a[2]), "r"(a[3]), "r"(b[0]), "r"(b[1]));
}
#define CP_ASYNC16(dst, src)                                                   \
    asm volatile("cp.async.cg.shared.global [%0], [%1], 16;"                   \
                 :: "r"(dst), "l"(src) : "memory")
#define CP_COMMIT()  asm volatile("cp.async.commit_group;" ::: "memory")
#define CP_WAIT(n)   asm volatile("cp.async.wait_group %0;" :: "n"(n) : "memory")

// ---------------- K0: probe gt dtype (int64 vs int32) ----------------
__global__ void k_probe(const void* __restrict__ gt, int B, int C) {
    const long long* p = (const long long*)gt;
    int t = threadIdx.x;
    int bad = 0;
    for (int i = t; i < B; i += 256) {
        long long v = p[i];
        if (v < 0 || v >= (long long)C) bad = 1;
    }
    __shared__ int sh[256];
    sh[t] = bad; __syncthreads();
    for (int o = 128; o > 0; o >>= 1) { if (t < o) sh[t] |= sh[t + o]; __syncthreads(); }
    if (t == 0) g_gt_is_i32 = sh[0];
}

// ---------------- K1: normalize embedding rows (fp32 + bf16 copies) ----------------
__global__ void k_norm_e(const float* __restrict__ e) {
    int b = blockIdx.x, t = threadIdx.x;
    float ss = 0.f;
    for (int d = t; d < ND; d += 256) { float v = e[(size_t)b * ND + d]; ss += v * v; }
    __shared__ float sh[256];
    sh[t] = ss; __syncthreads();
    for (int o = 128; o > 0; o >>= 1) { if (t < o) sh[t] += sh[t + o]; __syncthreads(); }
    float rn = rsqrtf(sh[0]);
    for (int d = t; d < ND; d += 256) {
        float v = e[(size_t)b * ND + d] * rn;
        g_en [(size_t)b * ND + d] = v;
        g_ebf[(size_t)b * ND + d] = __float2bfloat16(v);
    }
}

// ---------------- K3: per-sample pos/phi (fp32 exact) ----------------
__global__ void k_phi(const float* __restrict__ w, const void* __restrict__ gt, int C) {
    int b = blockIdx.x, t = threadIdx.x;
    __shared__ int sg;
    if (t == 0) {
        long long v;
        if (g_gt_is_i32) v = (long long)((const int*)gt)[b];
        else             v = ((const long long*)gt)[b];
        if (v < 0) v = 0;
        if (v >= C) v = C - 1;
        sg = (int)v;
    }
    __syncthreads();
    int g = sg;
    const float* er = g_en + (size_t)b * ND;
    const float* wr = w + (size_t)g * ND;
    float s = 0.f, q = 0.f;
    for (int d = t; d < ND; d += 256) { float wv = wr[d]; s += er[d] * wv; q += wv * wv; }
    __shared__ float shs[256], shq[256];
    shs[t] = s; shq[t] = q; __syncthreads();
    for (int o = 128; o > 0; o >>= 1) {
        if (t < o) { shs[t] += shs[t + o]; shq[t] += shq[t + o]; }
        __syncthreads();
    }
    if (t == 0) {
        float pos = shs[0] * rsqrtf(shq[0]);
        pos = fminf(fmaxf(pos, -1.f + ARC_EPS), 1.f - ARC_EPS);
        float s2 = fminf(fmaxf(1.f - pos * pos, ARC_EPS), 1.f - ARC_EPS);
        float ph = pos * ARC_COS_M - sqrtf(s2) * ARC_SIN_M;
        if (!(pos > ARC_TH)) ph = pos - ARC_MM;
        g_phi[b] = ph;
        g_gt[b] = g;
    }
}

// ---------------- K4: HMMA GEMM + margin + partial sum-exp ----------------
// 256 threads, 8 warps: warp_m(2) x warp_n(4); warp tile 64 cls x 64 smp
// (8 LDSM : 32 MMA per k-step = 1.0 wavefront/MMA).
// CTA tile 128 cls x 256 smp; persistent W; E chunks double-buffered cp.async.
// SMEM: W bf16 [128 cls][512 k] (128KB, 1024B rows, swizzled)
//     + E bf16 2 x [256 smp][64 k] (2x32KB, 128B rows, swizzled)
//     + winv[128] + phi[256] + gt[256]
#define SM_W 0
#define SM_E (CTILE * ND * 2)                  // 131072
#define E_BUF (STILE * KCH * 2)                // 32768
#define SM_WINV (SM_E + 2 * E_BUF)             // 196608
#define SM_PHI  (SM_WINV + CTILE * 4)          // 197120
#define SM_GT   (SM_PHI + STILE * 4)           // 198144
#define SMEM_NEED (SM_GT + STILE * 4 + 128)    // 199296

__global__ __launch_bounds__(256, 1) void k_gemm(const float* __restrict__ w,
                                                 int B, int C, int npart) {
    extern __shared__ char smp[];
    const uint32_t sb = s2u(smp);
    float* winv_sm = (float*)(smp + SM_WINV);
    float* phi_sm  = (float*)(smp + SM_PHI);
    int*   gt_sm   = (int*)  (smp + SM_GT);

    const int t    = threadIdx.x;
    const int wid  = t >> 5;
    const int lane = t & 31;
    const int warp_m = wid >> 2;   // 0..1 : 64 classes each
    const int warp_n = wid & 3;    // 0..3 : 64 samples each
    const int cn0  = blockIdx.x * CTILE;

    // E chunk loader (cp.async): 256 rows x 128B; 1 thread/row, 8 x 16B
    const int eRow = t;
    const uint32_t eDstRow = sb + SM_E + (uint32_t)eRow * 128u;
    const uint32_t eSwz    = (uint32_t)((eRow & 7) << 4);

#define ISSUE_E(kh, buf, s0) do {                                                \
    unsigned long long _src = __cvta_generic_to_global(                          \
        g_ebf + (size_t)((s0) + eRow) * ND + (kh) * KCH);                        \
    uint32_t _dst = eDstRow + (uint32_t)((buf) * E_BUF);                         \
    CP_ASYNC16(_dst + (((uint32_t)(0 * 16)) ^ eSwz), _src);                      \
    CP_ASYNC16(_dst + (((uint32_t)(1 * 16)) ^ eSwz), _src + 16);                 \
    CP_ASYNC16(_dst + (((uint32_t)(2 * 16)) ^ eSwz), _src + 32);                 \
    CP_ASYNC16(_dst + (((uint32_t)(3 * 16)) ^ eSwz), _src + 48);                 \
    CP_ASYNC16(_dst + (((uint32_t)(4 * 16)) ^ eSwz), _src + 64);                 \
    CP_ASYNC16(_dst + (((uint32_t)(5 * 16)) ^ eSwz), _src + 80);                 \
    CP_ASYNC16(_dst + (((uint32_t)(6 * 16)) ^ eSwz), _src + 96);                 \
    CP_ASYNC16(_dst + (((uint32_t)(7 * 16)) ^ eSwz), _src + 112);                \
    CP_COMMIT();                                                                 \
} while (0)

    // ---- Phase 1: W tile fp32 -> bf16 SMEM (1024B rows), fused sum-of-squares ----
    {
        const int clsLoc = t >> 1;          // 0..127
        const int half   = t & 1;           // k-half (256 elems each)
        const int clsG   = cn0 + clsLoc;
        const float* wr = w + (size_t)clsG * ND + half * 256;
        float ssq = 0.f;
        #pragma unroll 8
        for (int i = 0; i < 64; i++) {
            float4 v = make_float4(0.f, 0.f, 0.f, 0.f);
            if (clsG < C) v = *(const float4*)(wr + i * 4);
            ssq += v.x * v.x + v.y * v.y + v.z * v.z + v.w * v.w;
            __nv_bfloat162 lo = __float22bfloat162_rn(make_float2(v.x, v.y));
            __nv_bfloat162 hi = __float22bfloat162_rn(make_float2(v.z, v.w));
            uint2 pk;
            pk.x = *(uint32_t*)&lo;
            pk.y = *(uint32_t*)&hi;
            uint32_t koff = (uint32_t)((half * 256 + i * 4) * 2);
            *(uint2*)(smp + SM_W + clsLoc * 1024u + (koff ^ ((clsLoc & 7u) << 4))) = pk;
        }
        ssq += __shfl_xor_sync(0xffffffffu, ssq, 1);
        if (half == 0) winv_sm[clsLoc] = rsqrtf(ssq);
    }
    // phi/gt for sample tile 0
    phi_sm[t] = g_phi[t];
    gt_sm[t]  = g_gt[t];

    // ---- per-lane ldmatrix address components (loop-invariant) ----
    const uint32_t swzx  = (uint32_t)((lane & 7) << 4);
    // A frags (64cls x 16k): four x4 at class offsets 0,16,32,48 (1024B rows)
    const uint32_t aAddrBase = sb + SM_W + (uint32_t)(warp_m * 64 + (lane & 15)) * 1024u;
    const uint32_t kOffA  = (uint32_t)((lane >> 4) << 3);
    // B frags (64smp x 16k): four x4 at sample offsets 0,16,32,48 (128B rows)
    const uint32_t bRowLoc = (uint32_t)(((lane >> 4) << 3) + (lane & 7));
    const uint32_t bAddrBase = sb + SM_E + (uint32_t)(warp_n * 64 + bRowLoc) * 128u;
    const uint32_t kOffB  = (uint32_t)(((lane >> 3) & 1) << 3);

    const float HI = 1.f - ARC_EPS, LO = -1.f + ARC_EPS;
    const int nTiles = B / STILE;   // 2

    for (int st = 0; st < nTiles; st++) {
        const int s0 = st * STILE;

        float acc[4][8][4];
        #pragma unroll
        for (int mi = 0; mi < 4; mi++)
            #pragma unroll
            for (int ni = 0; ni < 8; ni++)
                #pragma unroll
                for (int q = 0; q < 4; q++) acc[mi][ni][q] = 0.f;

        ISSUE_E(0, 0, s0);

        #pragma unroll
        for (int kh = 0; kh < NCHK; kh++) {
            const int p = kh & 1;
            if (kh + 1 < NCHK) ISSUE_E(kh + 1, p ^ 1, s0);
            if (kh + 1 < NCHK) { CP_WAIT(1); } else { CP_WAIT(0); }
            __syncthreads();   // chunk p data visible to all warps

            const uint32_t bBuf = bAddrBase + (uint32_t)(p * E_BUF);
            #pragma unroll
            for (int k0 = 0; k0 < KCH; k0 += 16) {
                uint32_t offA = (((uint32_t)(kh * KCH + k0) + kOffA) << 1) ^ swzx;
                uint32_t offB = (((uint32_t)k0 + kOffB) << 1) ^ swzx;
                uint32_t a[4][4], b[8][2];
                LDSM_X4(a[0][0], a[0][1], a[0][2], a[0][3], aAddrBase + offA);
                LDSM_X4(a[1][0], a[1][1], a[1][2], a[1][3], aAddrBase + 16u * 1024u + offA);
                LDSM_X4(a[2][0], a[2][1], a[2][2], a[2][3], aAddrBase + 32u * 1024u + offA);
                LDSM_X4(a[3][0], a[3][1], a[3][2], a[3][3], aAddrBase + 48u * 1024u + offA);
                LDSM_X4(b[0][0], b[0][1], b[1][0], b[1][1], bBuf + offB);
                LDSM_X4(b[2][0], b[2][1], b[3][0], b[3][1], bBuf + 16u * 128u + offB);
                LDSM_X4(b[4][0], b[4][1], b[5][0], b[5][1], bBuf + 32u * 128u + offB);
                LDSM_X4(b[6][0], b[6][1], b[7][0], b[7][1], bBuf + 48u * 128u + offB);
                #pragma unroll
                for (int mi = 0; mi < 4; mi++)
                    #pragma unroll
                    for (int ni = 0; ni < 8; ni++)
                        mma16816(acc[mi][ni], a[mi], b[ni]);
            }
            __syncthreads();   // buffer p consumed, safe to refill
        }

        // ---- epilogue: margin transform + fixed-max sum-exp ----
        // acc[mi][ni][rh*2+i]: class = warp_m*64 + mi*16 + (lane>>2) + rh*8
        //                      sample = warp_n*64 + ni*8 + 2*(lane&3) + i
        #pragma unroll
        for (int ni = 0; ni < 8; ni++) {
            #pragma unroll
            for (int i = 0; i < 2; i++) {
                const int sLoc = warp_n * 64 + ni * 8 + 2 * (lane & 3) + i;
                const float ph = phi_sm[sLoc];
                const int   gi = gt_sm[sLoc];
                float sum = 0.f;
                #pragma unroll
                for (int mi = 0; mi < 4; mi++) {
                    #pragma unroll
                    for (int rh = 0; rh < 2; rh++) {
                        const int clsLoc = warp_m * 64 + mi * 16 + (lane >> 2) + rh * 8;
                        const int c = cn0 + clsLoc;
                        if (c < C) {
                            float cv = acc[mi][ni][rh * 2 + i] * winv_sm[clsLoc];
                            cv = fminf(fmaxf(cv, LO), HI);
                            float v = (cv > ph) ? fmaf(1.2f, cv, 0.2f) : cv;
                            if (c == gi) v = ph;
                            sum += __expf(fmaf(v, ARC_SCALE, -FIX_MAX));
                        }
                    }
                }
                // reduce across the 8 lanes holding this sample (lane>>2 = 0..7)
                sum += __shfl_xor_sync(0xffffffffu, sum, 4);
                sum += __shfl_xor_sync(0xffffffffu, sum, 8);
                sum += __shfl_xor_sync(0xffffffffu, sum, 16);
                if ((lane >> 2) == 0)
                    g_part[(size_t)(s0 + sLoc) * npart + blockIdx.x * 2 + warp_m] = sum;
            }
        }

        // phi/gt for the next sample tile (after all epilogue reads)
        if (st + 1 < nTiles) {
            __syncthreads();
            phi_sm[t] = g_phi[(st + 1) * STILE + t];
            gt_sm[t]  = g_gt[(st + 1) * STILE + t];
        }
    }
#undef ISSUE_E
}

// ---------------- K5: per-sample combine (plain sum, fixed max) ----------------
__global__ void k_lse(int npart) {
    int b = blockIdx.x, t = threadIdx.x;
    const float* p = g_part + (size_t)b * npart;
    float s = 0.f;
    for (int i = t; i < npart; i += 256) s += p[i];
    __shared__ float sh[256];
    sh[t] = s; __syncthreads();
    for (int o = 128; o > 0; o >>= 1) { if (t < o) sh[t] += sh[t + o]; __syncthreads(); }
    if (t == 0) g_samp[b] = FIX_MAX + logf(sh[0]) - ARC_SCALE * g_phi[b];
}

// ---------------- K6: mean -> loss ----------------
__global__ void k_loss(float* __restrict__ out, int B) {
    int t = threadIdx.x;
    float s = 0.f;
    for (int i = t; i < B; i += 256) s += g_samp[i];
    __shared__ float sh[256];
    sh[t] = s; __syncthreads();
    for (int o = 128; o > 0; o >>= 1) { if (t < o) sh[t] += sh[t + o]; __syncthreads(); }
    if (t == 0) out[0] = sh[0] / (float)B;
}

// ---------------- launch ----------------
extern "C" void kernel_launch(void* const* d_in, const int* in_sizes, int n_in,
                              void* d_out, int out_size) {
    const float* emb = (const float*)d_in[0];
    const float* w   = (const float*)d_in[1];
    const void*  gt  = (const void*)d_in[2];
    float*       out = (float*)d_out;

    int B = in_sizes[2];
    int D = in_sizes[0] / B;     // 512
    int C = in_sizes[1] / D;     // 100000
    int nCblk = (C + CTILE - 1) / CTILE;
    int npart = nCblk * 2;

    static int smem_set = 0;
    if (!smem_set) {
        cudaFuncSetAttribute(k_gemm, cudaFuncAttributeMaxDynamicSharedMemorySize, SMEM_NEED);
        smem_set = 1;
    }

    k_probe<<<1, 256>>>(gt, B, C);
    k_norm_e<<<B, 256>>>(emb);
    k_phi<<<B, 256>>>(w, gt, C);
    k_gemm<<<nCblk, 256, SMEM_NEED>>>(w, B, C, npart);
    k_lse<<<B, 256>>>(npart);
    k_loss<<<1, 256>>>(out, B);
}

// round 16
// speedup vs baseline: 1.2591x; 1.2591x over previous
#include <cuda_runtime.h>
#include <cuda_bf16.h>
#include <math.h>
#include <stdint.h>

// ---------------- problem constants ----------------
#define NB 512          // batch
#define ND 512          // embed dim
#define MAX_C 100000
#define CTILE 128       // classes per class-tile (M)
#define STILE 256       // samples per sample tile (N)
#define KCH 64          // K chunk for E tile (double buffered)
#define NCHK (ND / KCH) // 8
#define NCBLK_MAX ((MAX_C + CTILE - 1) / CTILE)   // 782
#define NPART_MAX (NCBLK_MAX * 4)                 // 4 partials per class-tile
#define GRID_CAP 740    // 148 SMs x 5 waves (class-tile striding covers the rest)

// ArcFace constants (margin=0.5, scale=64, t=0.2)
#define ARC_COS_M 0.8775825618903728f
#define ARC_SIN_M 0.479425538604203f
#define ARC_TH   (-0.8775825618903728f)
#define ARC_MM    0.2397127693021015f
#define ARC_EPS   1e-7f
#define ARC_SCALE 64.0f
#define FIX_MAX   90.0f   // > 64*(1.2*1+0.2) = 89.6, absolute logit bound

// ---------------- static scratch ----------------
__device__ float          g_en [NB * ND];     // normalized embeddings fp32
__device__ __nv_bfloat16  g_ebf[NB * ND];     // normalized embeddings bf16
__device__ float          g_phi[NB];
__device__ int            g_gt [NB];
__device__ float          g_part[(size_t)NB * NPART_MAX];  // sum of exp(v-90)
__device__ float          g_samp[NB];
__device__ int            g_gt_is_i32;

// ---------------- PTX helpers (plain-sm_103-safe) ----------------
__device__ __forceinline__ uint32_t s2u(const void* p) {
    uint32_t a;
    asm("{ .reg .u64 t; cvta.to.shared.u64 t, %1; cvt.u32.u64 %0, t; }" : "=r"(a) : "l"(p));
    return a;
}
#define LDSM_X4(r0, r1, r2, r3, addr)                                          \
    asm volatile("ldmatrix.sync.aligned.m8n8.x4.shared.b16 {%0,%1,%2,%3}, [%4];" \
                 : "=r"(r0), "=r"(r1), "=r"(r2), "=r"(r3) : "r"(addr))
__device__ __forceinline__ void mma16816(float* c, const uint32_t* a, const uint32_t* b) {
    asm volatile(
        "mma.sync.aligned.m16n8k16.row.col.f32.bf16.bf16.f32 "
        "{%0,%1,%2,%3}, {%4,%5,%6,%7}, {%8,%9}, {%0,%1,%2,%3};"
        : "+f"(c[0]), "+f"(c[1]), "+f"(c[2]), "+f"(c[3])
        : "r"(a[0]), "r"(a[1]), "r"(a[2]), "r"(a[3]), "r"(b[0]), "r"(b[1]));
}
#define CP_ASYNC16(dst, src)                                                   \
    asm volatile("cp.async.cg.shared.global [%0], [%1], 16;"                   \
                 :: "r"(dst), "l"(src) : "memory")
#define CP_COMMIT()  asm volatile("cp.async.commit_group;" ::: "memory")
#define CP_WAIT0()   asm volatile("cp.async.wait_group 0;" ::: "memory")

// ---------------- K0: probe gt dtype (int64 vs int32) ----------------
__global__ void k_probe(const void* __restrict__ gt, int B, int C) {
    const long long* p = (const long long*)gt;
    int t = threadIdx.x;
    int bad = 0;
    for (int i = t; i < B; i += 256) {
        long long v = p[i];
        if (v < 0 || v >= (long long)C) bad = 1;
    }
    __shared__ int sh[256];
    sh[t] = bad; __syncthreads();
    for (int o = 128; o > 0; o >>= 1) { if (t < o) sh[t] |= sh[t + o]; __syncthreads(); }
    if (t == 0) g_gt_is_i32 = sh[0];
}

// ---------------- K1: normalize embedding rows (fp32 + bf16 copies) ----------------
__global__ void k_norm_e(const float* __restrict__ e) {
    int b = blockIdx.x, t = threadIdx.x;
    float ss = 0.f;
    for (int d = t; d < ND; d += 256) { float v = e[(size_t)b * ND + d]; ss += v * v; }
    __shared__ float sh[256];
    sh[t] = ss; __syncthreads();
    for (int o = 128; o > 0; o >>= 1) { if (t < o) sh[t] += sh[t + o]; __syncthreads(); }
    float rn = rsqrtf(sh[0]);
    for (int d = t; d < ND; d += 256) {
        float v = e[(size_t)b * ND + d] * rn;
        g_en [(size_t)b * ND + d] = v;
        g_ebf[(size_t)b * ND + d] = __float2bfloat16(v);
    }
}

// ---------------- K3: per-sample pos/phi (fp32 exact) ----------------
__global__ void k_phi(const float* __restrict__ w, const void* __restrict__ gt, int C) {
    int b = blockIdx.x, t = threadIdx.x;
    __shared__ int sg;
    if (t == 0) {
        long long v;
        if (g_gt_is_i32) v = (long long)((const int*)gt)[b];
        else             v = ((const long long*)gt)[b];
        if (v < 0) v = 0;
        if (v >= C) v = C - 1;
        sg = (int)v;
    }
    __syncthreads();
    int g = sg;
    const float* er = g_en + (size_t)b * ND;
    const float* wr = w + (size_t)g * ND;
    float s = 0.f, q = 0.f;
    for (int d = t; d < ND; d += 256) { float wv = wr[d]; s += er[d] * wv; q += wv * wv; }
    __shared__ float shs[256], shq[256];
    shs[t] = s; shq[t] = q; __syncthreads();
    for (int o = 128; o > 0; o >>= 1) {
        if (t < o) { shs[t] += shs[t + o]; shq[t] += shq[t + o]; }
        __syncthreads();
    }
    if (t == 0) {
        float pos = shs[0] * rsqrtf(shq[0]);
        pos = fminf(fmaxf(pos, -1.f + ARC_EPS), 1.f - ARC_EPS);
        float s2 = fminf(fmaxf(1.f - pos * pos, ARC_EPS), 1.f - ARC_EPS);
        float ph = pos * ARC_COS_M - sqrtf(s2) * ARC_SIN_M;
        if (!(pos > ARC_TH)) ph = pos - ARC_MM;
        g_phi[b] = ph;
        g_gt[b] = g;
    }
}

// ---------------- K4: HMMA GEMM + margin + partial sum-exp ----------------
// 512 threads, 16 warps: warp_m(4) x warp_n(4); warp tile 32 cls x 64 smp.
// Class-tile striding (grid 740 covers 782 tiles; first 42 CTAs do 2 tiles)
// to remove the 6th partial wave. E chunks double-buffered via cp.async with
// issue-after-sync ordering (safe) and a global chunk counter so loads overlap
// the W-convert phase and the epilogue.
#define SM_W 0
#define SM_E (CTILE * ND * 2)                  // 131072
#define E_BUF (STILE * KCH * 2)                // 32768
#define SM_WINV (SM_E + 2 * E_BUF)             // 196608
#define SM_PHI  (SM_WINV + CTILE * 4)          // 197120
#define SM_GT   (SM_PHI + STILE * 4)           // 198144
#define SMEM_NEED (SM_GT + STILE * 4 + 128)    // ~194.6KB

__global__ __launch_bounds__(512, 1) void k_gemm(const float* __restrict__ w,
                                                 int B, int C, int nCblk, int npart) {
    extern __shared__ char smp[];
    const uint32_t sb = s2u(smp);
    float* winv_sm = (float*)(smp + SM_WINV);
    float* phi_sm  = (float*)(smp + SM_PHI);
    int*   gt_sm   = (int*)  (smp + SM_GT);

    const int t    = threadIdx.x;
    const int wid  = t >> 5;
    const int lane = t & 31;
    const int warp_m = wid >> 2;   // 0..3 : 32 classes each
    const int warp_n = wid & 3;    // 0..3 : 64 samples each

    // E chunk loader (cp.async): 256 rows x 128B; 2 threads/row, 4 x 16B each
    const int eRow   = t >> 1;              // 0..255
    const int eUbase = (t & 1) * 4;         // 16B-unit base within row
    const uint32_t eDstRow = sb + SM_E + (uint32_t)eRow * 128u;
    const uint32_t eSwz    = (uint32_t)((eRow & 7) << 4);

    // chunk index ci in [0, 2*NCHK): tile = ci>>3, k-chunk = ci&7, buf = ci&1
#define ISSUE_CHUNK(ci) do {                                                     \
    int _s0 = ((ci) >> 3) * STILE;                                               \
    int _kh = (ci) & 7;                                                          \
    unsigned long long _src = __cvta_generic_to_global(                          \
        g_ebf + (size_t)(_s0 + eRow) * ND + _kh * KCH + eUbase * 8);             \
    uint32_t _dst = eDstRow + (uint32_t)(((ci) & 1) * E_BUF);                    \
    CP_ASYNC16(_dst + (((uint32_t)((eUbase + 0) * 16)) ^ eSwz), _src);           \
    CP_ASYNC16(_dst + (((uint32_t)((eUbase + 1) * 16)) ^ eSwz), _src + 16);      \
    CP_ASYNC16(_dst + (((uint32_t)((eUbase + 2) * 16)) ^ eSwz), _src + 32);      \
    CP_ASYNC16(_dst + (((uint32_t)((eUbase + 3) * 16)) ^ eSwz), _src + 48);      \
    CP_COMMIT();                                                                 \
} while (0)

    // ---- per-lane ldmatrix address components (loop-invariant) ----
    const uint32_t swzx  = (uint32_t)((lane & 7) << 4);
    const uint32_t aAddr0 = sb + SM_W + (uint32_t)(warp_m * 32 + (lane & 15)) * 1024u;
    const uint32_t aAddr1 = aAddr0 + 16u * 1024u;
    const uint32_t kOffA  = (uint32_t)((lane >> 4) << 3);
    const uint32_t bRowLoc = (uint32_t)(((lane >> 4) << 3) + (lane & 7));
    const uint32_t bAddrBase = sb + SM_E + (uint32_t)(warp_n * 64 + bRowLoc) * 128u;
    const uint32_t kOffB  = (uint32_t)(((lane >> 3) & 1) << 3);

    const float HI = 1.f - ARC_EPS, LO = -1.f + ARC_EPS;
    const int nTiles = B / STILE;            // 2
    const int totChunks = nTiles * NCHK;     // 16

    for (int ct = blockIdx.x; ct < nCblk; ct += gridDim.x) {
        const int cn0 = ct * CTILE;
        if (ct != (int)blockIdx.x) __syncthreads();  // prior epilogue done before W overwrite

        // chunk 0 flies during the W-convert phase
        ISSUE_CHUNK(0);

        // ---- Phase 1: W tile fp32 -> bf16 SMEM, fused sum-of-squares ----
        {
            const int clsLoc = t >> 2;          // 0..127
            const int quar   = t & 3;           // k-quarter (128 elems each)
            const int clsG   = cn0 + clsLoc;
            const float* wr = w + (size_t)clsG * ND + quar * 128;
            float ssq = 0.f;
            #pragma unroll 8
            for (int i = 0; i < 32; i++) {
                float4 v = make_float4(0.f, 0.f, 0.f, 0.f);
                if (clsG < C) v = *(const float4*)(wr + i * 4);
                ssq += v.x * v.x + v.y * v.y + v.z * v.z + v.w * v.w;
                __nv_bfloat162 lo = __float22bfloat162_rn(make_float2(v.x, v.y));
                __nv_bfloat162 hi = __float22bfloat162_rn(make_float2(v.z, v.w));
                uint2 pk;
                pk.x = *(uint32_t*)&lo;
                pk.y = *(uint32_t*)&hi;
                uint32_t koff = (uint32_t)((quar * 128 + i * 4) * 2);
                *(uint2*)(smp + SM_W + clsLoc * 1024u + (koff ^ ((clsLoc & 7u) << 4))) = pk;
            }
            ssq += __shfl_xor_sync(0xffffffffu, ssq, 1);
            ssq += __shfl_xor_sync(0xffffffffu, ssq, 2);
            if (quar == 0) winv_sm[clsLoc] = rsqrtf(ssq);
        }
        // phi/gt for sample tile 0
        if (t < STILE) {
            phi_sm[t] = g_phi[t];
            gt_sm[t]  = g_gt[t];
        }

        for (int st = 0; st < nTiles; st++) {
            const int s0 = st * STILE;

            float acc[2][8][4];
            #pragma unroll
            for (int mi = 0; mi < 2; mi++)
                #pragma unroll
                for (int ni = 0; ni < 8; ni++)
                    #pragma unroll
                    for (int q = 0; q < 4; q++) acc[mi][ni][q] = 0.f;

            #pragma unroll
            for (int kh = 0; kh < NCHK; kh++) {
                const int ci = st * NCHK + kh;
                CP_WAIT0();                      // chunk ci landed
                __syncthreads();                 // all warps done with other buffer
                if (ci + 1 < totChunks) ISSUE_CHUNK(ci + 1);

                const uint32_t bBuf = bAddrBase + (uint32_t)((ci & 1) * E_BUF);
                #pragma unroll
                for (int k0 = 0; k0 < KCH; k0 += 16) {
                    uint32_t offA = (((uint32_t)(kh * KCH + k0) + kOffA) << 1) ^ swzx;
                    uint32_t offB = (((uint32_t)k0 + kOffB) << 1) ^ swzx;
                    uint32_t a0[4], a1[4], b[8][2];
                    LDSM_X4(a0[0], a0[1], a0[2], a0[3], aAddr0 + offA);
                    LDSM_X4(a1[0], a1[1], a1[2], a1[3], aAddr1 + offA);
                    LDSM_X4(b[0][0], b[0][1], b[1][0], b[1][1], bBuf + offB);
                    LDSM_X4(b[2][0], b[2][1], b[3][0], b[3][1], bBuf + 16u * 128u + offB);
                    LDSM_X4(b[4][0], b[4][1], b[5][0], b[5][1], bBuf + 32u * 128u + offB);
                    LDSM_X4(b[6][0], b[6][1], b[7][0], b[7][1], bBuf + 48u * 128u + offB);
                    #pragma unroll
                    for (int ni = 0; ni < 8; ni++) {
                        mma16816(acc[0][ni], a0, b[ni]);
                        mma16816(acc[1][ni], a1, b[ni]);
                    }
                }
            }

            // ---- epilogue: margin transform + fixed-max sum-exp ----
            // (next tile's chunk 0 is already in flight, overlapping this)
            #pragma unroll
            for (int ni = 0; ni < 8; ni++) {
                #pragma unroll
                for (int i = 0; i < 2; i++) {
                    const int sLoc = warp_n * 64 + ni * 8 + 2 * (lane & 3) + i;
                    const float ph = phi_sm[sLoc];
                    const int   gi = gt_sm[sLoc];
                    float sum = 0.f;
                    #pragma unroll
                    for (int mi = 0; mi < 2; mi++) {
                        #pragma unroll
                        for (int rh = 0; rh < 2; rh++) {
                            const int clsLoc = warp_m * 32 + mi * 16 + (lane >> 2) + rh * 8;
                            const int c = cn0 + clsLoc;
                            if (c < C) {
                                float cv = acc[mi][ni][rh * 2 + i] * winv_sm[clsLoc];
                                cv = fminf(fmaxf(cv, LO), HI);
                                float v = (cv > ph) ? fmaf(1.2f, cv, 0.2f) : cv;
                                if (c == gi) v = ph;
                                sum += __expf(fmaf(v, ARC_SCALE, -FIX_MAX));
                            }
                        }
                    }
                    sum += __shfl_xor_sync(0xffffffffu, sum, 4);
                    sum += __shfl_xor_sync(0xffffffffu, sum, 8);
                    sum += __shfl_xor_sync(0xffffffffu, sum, 16);
                    if ((lane >> 2) == 0)
                        g_part[(size_t)(s0 + sLoc) * npart + ct * 4 + warp_m] = sum;
                }
            }

            // phi/gt for the next sample tile (after all epilogue reads)
            if (st + 1 < nTiles) {
                __syncthreads();
                if (t < STILE) {
                    phi_sm[t] = g_phi[(st + 1) * STILE + t];
                    gt_sm[t]  = g_gt[(st + 1) * STILE + t];
                }
            }
        }
    }
#undef ISSUE_CHUNK
}

// ---------------- K5: per-sample combine (plain sum, fixed max) ----------------
__global__ void k_lse(int npart) {
    int b = blockIdx.x, t = threadIdx.x;
    const float* p = g_part + (size_t)b * npart;
    float s = 0.f;
    for (int i = t; i < npart; i += 256) s += p[i];
    __shared__ float sh[256];
    sh[t] = s; __syncthreads();
    for (int o = 128; o > 0; o >>= 1) { if (t < o) sh[t] += sh[t + o]; __syncthreads(); }
    if (t == 0) g_samp[b] = FIX_MAX + logf(sh[0]) - ARC_SCALE * g_phi[b];
}

// ---------------- K6: mean -> loss ----------------
__global__ void k_loss(float* __restrict__ out, int B) {
    int t = threadIdx.x;
    float s = 0.f;
    for (int i = t; i < B; i += 256) s += g_samp[i];
    __shared__ float sh[256];
    sh[t] = s; __syncthreads();
    for (int o = 128; o > 0; o >>= 1) { if (t < o) sh[t] += sh[t + o]; __syncthreads(); }
    if (t == 0) out[0] = sh[0] / (float)B;
}

// ---------------- launch ----------------
extern "C" void kernel_launch(void* const* d_in, const int* in_sizes, int n_in,
                              void* d_out, int out_size) {
    const float* emb = (const float*)d_in[0];
    const float* w   = (const float*)d_in[1];
    const void*  gt  = (const void*)d_in[2];
    float*       out = (float*)d_out;

    int B = in_sizes[2];
    int D = in_sizes[0] / B;     // 512
    int C = in_sizes[1] / D;     // 100000
    int nCblk = (C + CTILE - 1) / CTILE;     // 782
    int npart = nCblk * 4;
    int grid = nCblk < GRID_CAP ? nCblk : GRID_CAP;

    static int smem_set = 0;
    if (!smem_set) {
        cudaFuncSetAttribute(k_gemm, cudaFuncAttributeMaxDynamicSharedMemorySize, SMEM_NEED);
        smem_set = 1;
    }

    k_probe<<<1, 256>>>(gt, B, C);
    k_norm_e<<<B, 256>>>(emb);
    k_phi<<<B, 256>>>(w, gt, C);
    k_gemm<<<grid, 512, SMEM_NEED>>>(w, B, C, nCblk, npart);
    k_lse<<<B, 256>>>(npart);
    k_loss<<<1, 256>>>(out, B);
}

// round 17
// speedup vs baseline: 1.2832x; 1.0191x over previous
#include <cuda_runtime.h>
#include <cuda_bf16.h>
#include <math.h>
#include <stdint.h>

// ---------------- problem constants ----------------
#define NB 512          // batch
#define ND 512          // embed dim
#define MAX_C 100000
#define CTILE 128       // classes per class-tile (M)
#define STILE 256       // samples per sample tile (N)
#define KCH 64          // K chunk for E tile (double buffered)
#define NCHK (ND / KCH) // 8
#define NCBLK_MAX ((MAX_C + CTILE - 1) / CTILE)   // 782
#define NPART_MAX (NCBLK_MAX * 4)                 // 4 partials per class-tile
#define GRID_CAP 740    // 148 SMs x 5 waves (class-tile striding covers the rest)

// ArcFace constants (margin=0.5, scale=64, t=0.2)
#define ARC_COS_M 0.8775825618903728f
#define ARC_SIN_M 0.479425538604203f
#define ARC_TH   (-0.8775825618903728f)
#define ARC_MM    0.2397127693021015f
#define ARC_EPS   1e-7f
#define ARC_SCALE 64.0f
#define FIX_MAX   90.0f   // > 64*(1.2*1+0.2) = 89.6, absolute logit bound
// exp(v*64 - 90) == exp2(v*92.33248262 - 129.8425537)
#define EXP2_SCALE 92.33248261689366f
#define EXP2_BIAS  129.84255368000671f

// ---------------- static scratch ----------------
__device__ float          g_en [NB * ND];     // normalized embeddings fp32 (unused by gemm, kept for debug)
__device__ __nv_bfloat16  g_ebf[NB * ND];     // normalized embeddings bf16
__device__ float          g_phi[NB];
__device__ int            g_gt [NB];
__device__ float          g_part[(size_t)NB * NPART_MAX];  // sum of exp(v-90)
__device__ float          g_samp[NB];
__device__ int            g_gt_is_i32;
__device__ unsigned int   g_done;             // k_lse completion counter

// ---------------- PTX helpers (plain-sm_103-safe) ----------------
__device__ __forceinline__ uint32_t s2u(const void* p) {
    uint32_t a;
    asm("{ .reg .u64 t; cvta.to.shared.u64 t, %1; cvt.u32.u64 %0, t; }" : "=r"(a) : "l"(p));
    return a;
}
#define LDSM_X4(r0, r1, r2, r3, addr)                                          \
    asm volatile("ldmatrix.sync.aligned.m8n8.x4.shared.b16 {%0,%1,%2,%3}, [%4];" \
                 : "=r"(r0), "=r"(r1), "=r"(r2), "=r"(r3) : "r"(addr))
__device__ __forceinline__ void mma16816(float* c, const uint32_t* a, const uint32_t* b) {
    asm volatile(
        "mma.sync.aligned.m16n8k16.row.col.f32.bf16.bf16.f32 "
        "{%0,%1,%2,%3}, {%4,%5,%6,%7}, {%8,%9}, {%0,%1,%2,%3};"
        : "+f"(c[0]), "+f"(c[1]), "+f"(c[2]), "+f"(c[3])
        : "r"(a[0]), "r"(a[1]), "r"(a[2]), "r"(a[3]), "r"(b[0]), "r"(b[1]));
}
#define CP_ASYNC16(dst, src)                                                   \
    asm volatile("cp.async.cg.shared.global [%0], [%1], 16;"                   \
                 :: "r"(dst), "l"(src) : "memory")
#define CP_COMMIT()  asm volatile("cp.async.commit_group;" ::: "memory")
#define CP_WAIT0()   asm volatile("cp.async.wait_group 0;" ::: "memory")

// ---------------- K0: probe gt dtype + reset completion counter ----------------
__global__ void k_probe(const void* __restrict__ gt, int B, int C) {
    const long long* p = (const long long*)gt;
    int t = threadIdx.x;
    int bad = 0;
    for (int i = t; i < B; i += 256) {
        long long v = p[i];
        if (v < 0 || v >= (long long)C) bad = 1;
    }
    __shared__ int sh[256];
    sh[t] = bad; __syncthreads();
    for (int o = 128; o > 0; o >>= 1) { if (t < o) sh[t] |= sh[t + o]; __syncthreads(); }
    if (t == 0) { g_gt_is_i32 = sh[0]; g_done = 0u; }
}

// ---------------- K1: fused normalize-e + phi (one pass over e and w_gt) ----------------
__global__ void k_prep(const float* __restrict__ e, const float* __restrict__ w,
                       const void* __restrict__ gt, int C) {
    int b = blockIdx.x, t = threadIdx.x;
    __shared__ int sg;
    if (t == 0) {
        long long v;
        if (g_gt_is_i32) v = (long long)((const int*)gt)[b];
        else             v = ((const long long*)gt)[b];
        if (v < 0) v = 0;
        if (v >= C) v = C - 1;
        sg = (int)v;
    }
    __syncthreads();
    int g = sg;
    const float* er = e + (size_t)b * ND;
    const float* wr = w + (size_t)g * ND;

    // each thread owns 2 elements (256 thr x 2 = 512)
    float e0 = er[t], e1 = er[t + 256];
    float w0 = wr[t], w1 = wr[t + 256];
    float se = e0 * e0 + e1 * e1;
    float sw = w0 * w0 + w1 * w1;
    float sx = e0 * w0 + e1 * w1;

    __shared__ float she[256], shw[256], shx[256];
    she[t] = se; shw[t] = sw; shx[t] = sx;
    __syncthreads();
    for (int o = 128; o > 0; o >>= 1) {
        if (t < o) { she[t] += she[t + o]; shw[t] += shw[t + o]; shx[t] += shx[t + o]; }
        __syncthreads();
    }
    float rn = rsqrtf(she[0]);
    float v0 = e0 * rn, v1 = e1 * rn;
    g_en [(size_t)b * ND + t]       = v0;
    g_en [(size_t)b * ND + t + 256] = v1;
    g_ebf[(size_t)b * ND + t]       = __float2bfloat16(v0);
    g_ebf[(size_t)b * ND + t + 256] = __float2bfloat16(v1);

    if (t == 0) {
        float pos = shx[0] * rsqrtf(she[0] * shw[0]);
        pos = fminf(fmaxf(pos, -1.f + ARC_EPS), 1.f - ARC_EPS);
        float s2 = fminf(fmaxf(1.f - pos * pos, ARC_EPS), 1.f - ARC_EPS);
        float ph = pos * ARC_COS_M - sqrtf(s2) * ARC_SIN_M;
        if (!(pos > ARC_TH)) ph = pos - ARC_MM;
        g_phi[b] = ph;
        g_gt[b] = g;
    }
}

// ---------------- K4: HMMA GEMM + margin + partial sum-exp ----------------
// 512 threads, 16 warps: warp_m(4) x warp_n(4); warp tile 32 cls x 64 smp.
// Class-tile striding (grid 740 covers 782 tiles). E chunks double-buffered
// cp.async; LDSM groups interleaved into the MMA train.
#define SM_W 0
#define SM_E (CTILE * ND * 2)                  // 131072
#define E_BUF (STILE * KCH * 2)                // 32768
#define SM_WINV (SM_E + 2 * E_BUF)             // 196608
#define SM_PHI  (SM_WINV + CTILE * 4)          // 197120
#define SM_GT   (SM_PHI + STILE * 4)           // 198144
#define SMEM_NEED (SM_GT + STILE * 4 + 128)    // ~194.6KB

__global__ __launch_bounds__(512, 1) void k_gemm(const float* __restrict__ w,
                                                 int B, int C, int nCblk, int npart) {
    extern __shared__ char smp[];
    const uint32_t sb = s2u(smp);
    float* winv_sm = (float*)(smp + SM_WINV);
    float* phi_sm  = (float*)(smp + SM_PHI);
    int*   gt_sm   = (int*)  (smp + SM_GT);

    const int t    = threadIdx.x;
    const int wid  = t >> 5;
    const int lane = t & 31;
    const int warp_m = wid >> 2;   // 0..3 : 32 classes each
    const int warp_n = wid & 3;    // 0..3 : 64 samples each

    // E chunk loader (cp.async): 256 rows x 128B; 2 threads/row, 4 x 16B each
    const int eRow   = t >> 1;              // 0..255
    const int eUbase = (t & 1) * 4;         // 16B-unit base within row
    const uint32_t eDstRow = sb + SM_E + (uint32_t)eRow * 128u;
    const uint32_t eSwz    = (uint32_t)((eRow & 7) << 4);

    // chunk index ci in [0, 2*NCHK): tile = ci>>3, k-chunk = ci&7, buf = ci&1
#define ISSUE_CHUNK(ci) do {                                                     \
    int _s0 = ((ci) >> 3) * STILE;                                               \
    int _kh = (ci) & 7;                                                          \
    unsigned long long _src = __cvta_generic_to_global(                          \
        g_ebf + (size_t)(_s0 + eRow) * ND + _kh * KCH + eUbase * 8);             \
    uint32_t _dst = eDstRow + (uint32_t)(((ci) & 1) * E_BUF);                    \
    CP_ASYNC16(_dst + (((uint32_t)((eUbase + 0) * 16)) ^ eSwz), _src);           \
    CP_ASYNC16(_dst + (((uint32_t)((eUbase + 1) * 16)) ^ eSwz), _src + 16);      \
    CP_ASYNC16(_dst + (((uint32_t)((eUbase + 2) * 16)) ^ eSwz), _src + 32);      \
    CP_ASYNC16(_dst + (((uint32_t)((eUbase + 3) * 16)) ^ eSwz), _src + 48);      \
    CP_COMMIT();                                                                 \
} while (0)

    // ---- per-lane ldmatrix address components (loop-invariant) ----
    const uint32_t swzx  = (uint32_t)((lane & 7) << 4);
    const uint32_t aAddr0 = sb + SM_W + (uint32_t)(warp_m * 32 + (lane & 15)) * 1024u;
    const uint32_t aAddr1 = aAddr0 + 16u * 1024u;
    const uint32_t kOffA  = (uint32_t)((lane >> 4) << 3);
    const uint32_t bRowLoc = (uint32_t)(((lane >> 4) << 3) + (lane & 7));
    const uint32_t bAddrBase = sb + SM_E + (uint32_t)(warp_n * 64 + bRowLoc) * 128u;
    const uint32_t kOffB  = (uint32_t)(((lane >> 3) & 1) << 3);

    const float HI = 1.f - ARC_EPS, LO = -1.f + ARC_EPS;
    const int nTiles = B / STILE;            // 2
    const int totChunks = nTiles * NCHK;     // 16

    for (int ct = blockIdx.x; ct < nCblk; ct += gridDim.x) {
        const int cn0 = ct * CTILE;
        if (ct != (int)blockIdx.x) __syncthreads();  // prior epilogue done before W overwrite

        // chunk 0 flies during the W-convert phase
        ISSUE_CHUNK(0);

        // ---- Phase 1: W tile fp32 -> bf16 SMEM, fused sum-of-squares ----
        {
            const int clsLoc = t >> 2;          // 0..127
            const int quar   = t & 3;           // k-quarter (128 elems each)
            const int clsG   = cn0 + clsLoc;
            const float* wr = w + (size_t)clsG * ND + quar * 128;
            float ssq = 0.f;
            #pragma unroll 8
            for (int i = 0; i < 32; i++) {
                float4 v = make_float4(0.f, 0.f, 0.f, 0.f);
                if (clsG < C) v = *(const float4*)(wr + i * 4);
                ssq += v.x * v.x + v.y * v.y + v.z * v.z + v.w * v.w;
                __nv_bfloat162 lo = __float22bfloat162_rn(make_float2(v.x, v.y));
                __nv_bfloat162 hi = __float22bfloat162_rn(make_float2(v.z, v.w));
                uint2 pk;
                pk.x = *(uint32_t*)&lo;
                pk.y = *(uint32_t*)&hi;
                uint32_t koff = (uint32_t)((quar * 128 + i * 4) * 2);
                *(uint2*)(smp + SM_W + clsLoc * 1024u + (koff ^ ((clsLoc & 7u) << 4))) = pk;
            }
            ssq += __shfl_xor_sync(0xffffffffu, ssq, 1);
            ssq += __shfl_xor_sync(0xffffffffu, ssq, 2);
            if (quar == 0) winv_sm[clsLoc] = rsqrtf(ssq);
        }
        // phi/gt for sample tile 0
        if (t < STILE) {
            phi_sm[t] = g_phi[t];
            gt_sm[t]  = g_gt[t];
        }

        for (int st = 0; st < nTiles; st++) {
            const int s0 = st * STILE;

            float acc[2][8][4];
            #pragma unroll
            for (int mi = 0; mi < 2; mi++)
                #pragma unroll
                for (int ni = 0; ni < 8; ni++)
                    #pragma unroll
                    for (int q = 0; q < 4; q++) acc[mi][ni][q] = 0.f;

            #pragma unroll
            for (int kh = 0; kh < NCHK; kh++) {
                const int ci = st * NCHK + kh;
                CP_WAIT0();                      // chunk ci landed
                __syncthreads();                 // all warps done with other buffer
                if (ci + 1 < totChunks) ISSUE_CHUNK(ci + 1);

                const uint32_t bBuf = bAddrBase + (uint32_t)((ci & 1) * E_BUF);
                #pragma unroll
                for (int k0 = 0; k0 < KCH; k0 += 16) {
                    uint32_t offA = (((uint32_t)(kh * KCH + k0) + kOffA) << 1) ^ swzx;
                    uint32_t offB = (((uint32_t)k0 + kOffB) << 1) ^ swzx;
                    uint32_t a0[4], a1[4], b[8][2];
                    // first LDSM group: A + first half of B
                    LDSM_X4(a0[0], a0[1], a0[2], a0[3], aAddr0 + offA);
                    LDSM_X4(a1[0], a1[1], a1[2], a1[3], aAddr1 + offA);
                    LDSM_X4(b[0][0], b[0][1], b[1][0], b[1][1], bBuf + offB);
                    LDSM_X4(b[2][0], b[2][1], b[3][0], b[3][1], bBuf + 16u * 128u + offB);
                    // second half of B issues under the first MMA burst
                    LDSM_X4(b[4][0], b[4][1], b[5][0], b[5][1], bBuf + 32u * 128u + offB);
                    LDSM_X4(b[6][0], b[6][1], b[7][0], b[7][1], bBuf + 48u * 128u + offB);
                    #pragma unroll
                    for (int ni = 0; ni < 4; ni++) {
                        mma16816(acc[0][ni], a0, b[ni]);
                        mma16816(acc[1][ni], a1, b[ni]);
                    }
                    #pragma unroll
                    for (int ni = 4; ni < 8; ni++) {
                        mma16816(acc[0][ni], a0, b[ni]);
                        mma16816(acc[1][ni], a1, b[ni]);
                    }
                }
            }

            // ---- epilogue: margin transform + fixed-max sum-exp (exp2 form) ----
            #pragma unroll
            for (int ni = 0; ni < 8; ni++) {
                #pragma unroll
                for (int i = 0; i < 2; i++) {
                    const int sLoc = warp_n * 64 + ni * 8 + 2 * (lane & 3) + i;
                    const float ph = phi_sm[sLoc];
                    const int   gi = gt_sm[sLoc];
                    float sum = 0.f;
                    #pragma unroll
                    for (int mi = 0; mi < 2; mi++) {
                        #pragma unroll
                        for (int rh = 0; rh < 2; rh++) {
                            const int clsLoc = warp_m * 32 + mi * 16 + (lane >> 2) + rh * 8;
                            const int c = cn0 + clsLoc;
                            if (c < C) {
                                float cv = acc[mi][ni][rh * 2 + i] * winv_sm[clsLoc];
                                cv = fminf(fmaxf(cv, LO), HI);
                                float v = (cv > ph) ? fmaf(1.2f, cv, 0.2f) : cv;
                                if (c == gi) v = ph;
                                sum += exp2f(fmaf(v, EXP2_SCALE, -EXP2_BIAS));
                            }
                        }
                    }
                    sum += __shfl_xor_sync(0xffffffffu, sum, 4);
                    sum += __shfl_xor_sync(0xffffffffu, sum, 8);
                    sum += __shfl_xor_sync(0xffffffffu, sum, 16);
                    if ((lane >> 2) == 0)
                        g_part[(size_t)(s0 + sLoc) * npart + ct * 4 + warp_m] = sum;
                }
            }

            // phi/gt for the next sample tile (after all epilogue reads)
            if (st + 1 < nTiles) {
                __syncthreads();
                if (t < STILE) {
                    phi_sm[t] = g_phi[(st + 1) * STILE + t];
                    gt_sm[t]  = g_gt[(st + 1) * STILE + t];
                }
            }
        }
    }
#undef ISSUE_CHUNK
}

// ---------------- K5: per-sample combine + (last block) mean -> loss ----------------
__global__ void k_lse(float* __restrict__ out, int B, int npart) {
    int b = blockIdx.x, t = threadIdx.x;
    const float* p = g_part + (size_t)b * npart;
    float s = 0.f;
    for (int i = t; i < npart; i += 256) s += p[i];
    __shared__ float sh[256];
    sh[t] = s; __syncthreads();
    for (int o = 128; o > 0; o >>= 1) { if (t < o) sh[t] += sh[t + o]; __syncthreads(); }
    __shared__ int last;
    if (t == 0) {
        g_samp[b] = FIX_MAX + logf(sh[0]) - ARC_SCALE * g_phi[b];
        __threadfence();
        unsigned int done = atomicAdd(&g_done, 1u);
        last = (done == (unsigned int)(gridDim.x - 1)) ? 1 : 0;
    }
    __syncthreads();
    if (last) {
        // final deterministic reduction by the last block
        float acc = 0.f;
        for (int i = t; i < B; i += 256) acc += g_samp[i];
        __shared__ float sh2[256];
        sh2[t] = acc; __syncthreads();
        for (int o = 128; o > 0; o >>= 1) { if (t < o) sh2[t] += sh2[t + o]; __syncthreads(); }
        if (t == 0) out[0] = sh2[0] / (float)B;
    }
}

// ---------------- launch ----------------
extern "C" void kernel_launch(void* const* d_in, const int* in_sizes, int n_in,
                              void* d_out, int out_size) {
    const float* emb = (const float*)d_in[0];
    const float* w   = (const float*)d_in[1];
    const void*  gt  = (const void*)d_in[2];
    float*       out = (float*)d_out;

    int B = in_sizes[2];
    int D = in_sizes[0] / B;     // 512
    int C = in_sizes[1] / D;     // 100000
    int nCblk = (C + CTILE - 1) / CTILE;     // 782
    int npart = nCblk * 4;
    int grid = nCblk < GRID_CAP ? nCblk : GRID_CAP;

    static int smem_set = 0;
    if (!smem_set) {
        cudaFuncSetAttribute(k_gemm, cudaFuncAttributeMaxDynamicSharedMemorySize, SMEM_NEED);
        smem_set = 1;
    }

    k_probe<<<1, 256>>>(gt, B, C);
    k_prep<<<B, 256>>>(emb, w, gt, C);
    k_gemm<<<grid, 512, SMEM_NEED>>>(w, B, C, nCblk, npart);
    k_lse<<<B, 256>>>(out, B, npart);
}